// round 7
// baseline (speedup 1.0000x reference)
#include <cuda_runtime.h>
#include <cuda_bf16.h>
#include <math.h>
#include <stdint.h>

// ---------------- constants ----------------
#define Bb 4
#define Cc 48
#define Tt 512
#define Ff 65
#define L0 62
#define L1 509
#define N0 2048        // B*T   (intra seqs)
#define N1 260         // B*F   (inter seqs)
#define ROWS0 126976   // N0*L0
#define ROWS1 132340   // N1*L1
#define ROWSMAX 132340
#define CONV_ROWS 133120  // 2048*65 == 260*512
#define XU_S  (ROWSMAX*192)
#define XW_S  ((size_t)ROWSMAX*768)
#define HS_S  ((size_t)ROWSMAX*384)
#define TSZ   (Bb*Cc*Tt*Ff)   // 6,389,760
#define EPSLN 1e-5f

// ---------------- device scratch ----------------
__device__ float g_xu[2*XU_S];
__device__ float g_xw[4*XW_S];
__device__ float g_hseq[2*HS_S];
__device__ float g_h[2*4*2048*192];
__device__ float g_c[4*2048*192];
__device__ float g_wihp[8*192*768];
__device__ float g_whhp[8*192*768];
__device__ float g_bp[8*768];
__device__ float g_twt[4*1536*48];
__device__ float g_io[2*TSZ];
__device__ float g_eo[2*TSZ];
__device__ float g_q[2*16*512*520];
__device__ float g_k[2*16*512*520];
__device__ float g_v[2*16*512*780];
__device__ float g_attn[(size_t)2*16*512*512];
__device__ float g_av[2*16*512*780];

__device__ __forceinline__ float sigf(float x){ return 1.f/(1.f+expf(-x)); }

#define GEMM_INNER \
  _Pragma("unroll") \
  for (int kk=0;kk<16;kk++){ \
    float a0=As[kk][ty4],a1=As[kk][ty4+1],a2=As[kk][ty4+2],a3=As[kk][ty4+3]; \
    float b0=Bs[kk][tx4],b1=Bs[kk][tx4+1],b2=Bs[kk][tx4+2],b3=Bs[kk][tx4+3]; \
    acc[0][0]+=a0*b0; acc[0][1]+=a0*b1; acc[0][2]+=a0*b2; acc[0][3]+=a0*b3; \
    acc[1][0]+=a1*b0; acc[1][1]+=a1*b1; acc[1][2]+=a1*b2; acc[1][3]+=a1*b3; \
    acc[2][0]+=a2*b0; acc[2][1]+=a2*b1; acc[2][2]+=a2*b2; acc[2][3]+=a2*b3; \
    acc[3][0]+=a3*b0; acc[3][1]+=a3*b1; acc[3][2]+=a3*b2; acc[3][3]+=a3*b3; \
  }

// ---------------- weight packing ----------------
__global__ void pack_weights(const float* __restrict__ LWih, const float* __restrict__ LWhh,
                             const float* __restrict__ Lb,   const float* __restrict__ TW)
{
    int stride = gridDim.x * blockDim.x;
    int t0 = blockIdx.x * blockDim.x + threadIdx.x;
    for (int idx = t0; idx < 8*192*768; idx += stride) {
        int w = idx / (192*768);
        int r = idx - w*(192*768);
        int j = r / 768, col = r - j*768;
        int u = col >> 2, gt = col & 3;
        int g = (w>>2)*2 + ((w>>1)&1);
        int d = w & 1;
        size_t src = ((size_t)(g*2+d)*768 + gt*192 + u);
        g_wihp[idx] = LWih[src*192 + j];
        g_whhp[idx] = LWhh[src*192 + j];
    }
    for (int idx = t0; idx < 8*768; idx += stride) {
        int w = idx / 768, col = idx - w*768;
        int u = col >> 2, gt = col & 3;
        int g = (w>>2)*2 + ((w>>1)&1);
        int d = w & 1;
        g_bp[idx] = Lb[(g*2+d)*768 + gt*192 + u];
    }
    for (int idx = t0; idx < 4*1536*48; idx += stride) {
        int g = idx / (1536*48);
        int r = idx - g*(1536*48);
        int kk = r / 48, o = r - kk*48;
        int k = kk / 384, i = kk - k*384;
        g_twt[idx] = TW[(((size_t)g*384 + i)*48 + o)*4 + k];
    }
}

__global__ void zero_state()
{
    int stride = gridDim.x * blockDim.x;
    int t0 = blockIdx.x * blockDim.x + threadIdx.x;
    for (int i = t0; i < 2*4*2048*192; i += stride) g_h[i] = 0.f;
    for (int i = t0; i < 4*2048*192;   i += stride) g_c[i] = 0.f;
}

// ---------------- LN over C + unfold, intra (seqs along F) ----------------
__global__ void ln_unfold_intra(const float* __restrict__ x0, const float* __restrict__ x1,
                                const float* __restrict__ ng, const float* __restrict__ nb)
{
    int t = blockIdx.x, b = blockIdx.y, s = blockIdx.z;
    const float* src = s ? x1 : x0;
    __shared__ float zs[48*65];
    __shared__ float mu[65], inv[65];
    int tid = threadIdx.x;
    for (int i = tid; i < 48*65; i += 256) {
        int c = i / 65, f = i - c*65;
        zs[i] = src[((size_t)(b*48 + c)*512 + t)*65 + f];
    }
    __syncthreads();
    if (tid < 65) {
        float s1 = 0.f, s2 = 0.f;
        #pragma unroll
        for (int c = 0; c < 48; ++c) { float v = zs[c*65 + tid]; s1 += v; s2 += v*v; }
        float m = s1 * (1.f/48.f);
        mu[tid] = m;
        inv[tid] = rsqrtf(s2*(1.f/48.f) - m*m + EPSLN);
    }
    __syncthreads();
    size_t n = (size_t)b*512 + t;
    float* outp = g_xu + (size_t)s*XU_S + n*(size_t)L0*192;
    for (int i = tid; i < 48*L0*4; i += 256) {
        int c = i / (L0*4);
        int r = i - c*(L0*4);
        int l = r >> 2, k = r & 3;
        int q = l + k;
        float v = (zs[c*65 + q] - mu[q]) * inv[q] * ng[s*48 + c] + nb[s*48 + c];
        outp[(size_t)l*192 + c*4 + k] = v;
    }
}

// ---------------- LN over C + unfold, inter (seqs along T) ----------------
__global__ void ln_unfold_inter(const float* __restrict__ ng, const float* __restrict__ nb)
{
    int t = blockIdx.x, b = blockIdx.y, s = blockIdx.z;
    const float* src = g_io + (size_t)s*TSZ;
    __shared__ float zs[48*65];
    __shared__ float mu[65], inv[65];
    int tid = threadIdx.x;
    for (int i = tid; i < 48*65; i += 256) {
        int c = i / 65, f = i - c*65;
        zs[i] = src[((size_t)(b*48 + c)*512 + t)*65 + f];
    }
    __syncthreads();
    if (tid < 65) {
        float s1 = 0.f, s2 = 0.f;
        #pragma unroll
        for (int c = 0; c < 48; ++c) { float v = zs[c*65 + tid]; s1 += v; s2 += v*v; }
        float m = s1 * (1.f/48.f);
        mu[tid] = m;
        inv[tid] = rsqrtf(s2*(1.f/48.f) - m*m + EPSLN);
    }
    __syncthreads();
    int gi = 2 + s;
    for (int i = tid; i < 48*65; i += 256) {
        int c = i / 65, f = i - c*65;
        float v = (zs[i] - mu[f]) * inv[f] * ng[gi*48 + c] + nb[gi*48 + c];
        size_t n = (size_t)b*65 + f;
        float* outp = g_xu + (size_t)s*XU_S + n*(size_t)L1*192;
        #pragma unroll
        for (int k = 0; k < 4; ++k) {
            int l = t - k;
            if (l >= 0 && l < L1) outp[(size_t)l*192 + c*4 + k] = v;
        }
    }
}

// ---------------- xw = xu @ Wih^T + b (packed cols) ----------------
__global__ void __launch_bounds__(256) xw_gemm(int phase, int M)
{
    __shared__ __align__(16) float As[16][68];
    __shared__ __align__(16) float Bs[16][68];
    int combo = blockIdx.z;
    int s = combo >> 1;
    const float* A  = g_xu + (size_t)s*XU_S;
    const float* Bw = g_wihp + (size_t)(phase*4 + combo)*192*768;
    const float* bias = g_bp + (size_t)(phase*4 + combo)*768;
    float* Co = g_xw + (size_t)combo*XW_S;
    int row0 = blockIdx.y*64, col0 = blockIdx.x*64;
    int tid = threadIdx.x, tx = tid & 15, ty = tid >> 4;
    int ty4 = ty*4, tx4 = tx*4;
    float acc[4][4] = {};
    for (int kc = 0; kc < 192; kc += 16) {
        int aRow = tid >> 2, kq = (tid & 3)*4;
        int gr = row0 + aRow; if (gr >= M) gr = M - 1;
        float4 av = *(const float4*)&A[(size_t)gr*192 + kc + kq];
        As[kq][aRow] = av.x; As[kq+1][aRow] = av.y; As[kq+2][aRow] = av.z; As[kq+3][aRow] = av.w;
        int bK = tid >> 4, nq = (tid & 15)*4;
        *(float4*)&Bs[bK][nq] = *(const float4*)&Bw[(size_t)(kc + bK)*768 + col0 + nq];
        __syncthreads();
        GEMM_INNER
        __syncthreads();
    }
    #pragma unroll
    for (int r = 0; r < 4; ++r) {
        int row = row0 + ty4 + r;
        if (row < M) {
            #pragma unroll
            for (int j = 0; j < 4; ++j)
                Co[(size_t)row*768 + col0 + tx4 + j] = acc[r][j] + bias[col0 + tx4 + j];
        }
    }
}

// ---------------- fused LSTM step ----------------
__global__ void __launch_bounds__(256) lstm_step(int t, int phase, int parity, int Nseq, int Lc)
{
    __shared__ __align__(16) float As[16][68];
    __shared__ __align__(16) float Bs[16][68];
    int combo = blockIdx.z;
    int s = combo >> 1, d = combo & 1;
    int tt = d ? (Lc - 1 - t) : t;
    const float* Ah = g_h + ((size_t)parity*4 + combo)*2048*192;
    float* Ho       = g_h + ((size_t)(parity ^ 1)*4 + combo)*2048*192;
    float* Cst      = g_c + (size_t)combo*2048*192;
    const float* Bw = g_whhp + (size_t)(phase*4 + combo)*192*768;
    const float* XW = g_xw + (size_t)combo*XW_S;
    float* hs = g_hseq + (size_t)s*HS_S;
    int row0 = blockIdx.y*64, col0 = blockIdx.x*64;
    int tid = threadIdx.x, tx = tid & 15, ty = tid >> 4;
    int ty4 = ty*4, tx4 = tx*4;
    float acc[4][4];
    #pragma unroll
    for (int r = 0; r < 4; ++r) {
        int row = row0 + ty4 + r;
        if (row < Nseq) {
            float4 v = *(const float4*)&XW[((size_t)row*Lc + tt)*768 + col0 + tx4];
            acc[r][0] = v.x; acc[r][1] = v.y; acc[r][2] = v.z; acc[r][3] = v.w;
        } else {
            acc[r][0] = acc[r][1] = acc[r][2] = acc[r][3] = 0.f;
        }
    }
    for (int kc = 0; kc < 192; kc += 16) {
        int aRow = tid >> 2, kq = (tid & 3)*4;
        int gr = row0 + aRow; if (gr >= Nseq) gr = Nseq - 1;
        float4 av = *(const float4*)&Ah[(size_t)gr*192 + kc + kq];
        As[kq][aRow] = av.x; As[kq+1][aRow] = av.y; As[kq+2][aRow] = av.z; As[kq+3][aRow] = av.w;
        int bK = tid >> 4, nq = (tid & 15)*4;
        *(float4*)&Bs[bK][nq] = *(const float4*)&Bw[(size_t)(kc + bK)*768 + col0 + nq];
        __syncthreads();
        GEMM_INNER
        __syncthreads();
    }
    int u = (col0 >> 2) + tx;
    #pragma unroll
    for (int r = 0; r < 4; ++r) {
        int row = row0 + ty4 + r;
        if (row < Nseq) {
            float ig = acc[r][0], fg = acc[r][1], gg = acc[r][2], og = acc[r][3];
            float cprev = Cst[(size_t)row*192 + u];
            float cn = sigf(fg)*cprev + sigf(ig)*tanhf(gg);
            float hn = sigf(og)*tanhf(cn);
            Cst[(size_t)row*192 + u] = cn;
            Ho[(size_t)row*192 + u] = hn;
            hs[((size_t)row*Lc + tt)*384 + d*192 + u] = hn;
        }
    }
}

// ---------------- convT1d as gather-GEMM + bias + residual ----------------
__global__ void __launch_bounds__(256) convt_gemm(int phase, const float* __restrict__ Tb,
                                                  const float* __restrict__ x0, const float* __restrict__ x1)
{
    __shared__ __align__(16) float As[16][68];
    __shared__ __align__(16) float Bs[16][68];
    int s = blockIdx.z;
    int Lc   = phase ? L1 : L0;
    int Qlen = phase ? 512 : 65;
    const float* hs = g_hseq + (size_t)s*HS_S;
    const float* Bw = g_twt + (size_t)(phase*2 + s)*1536*48;
    int row0 = blockIdx.y*64;
    int tid = threadIdx.x, tx = tid & 15, ty = tid >> 4;
    int ty4 = ty*4, tx4 = tx*4;
    float acc[4][4] = {};
    for (int kc = 0; kc < 1536; kc += 16) {
        int k  = kc / 384;
        int i0 = kc - k*384;
        int aRow = tid >> 2, kq = (tid & 3)*4;
        int gr = row0 + aRow;   // always < CONV_ROWS (2080*64 exact)
        int n = gr / Qlen, q = gr - n*Qlen;
        int l = q - k;
        float4 av = make_float4(0.f, 0.f, 0.f, 0.f);
        if (l >= 0 && l < Lc)
            av = *(const float4*)&hs[((size_t)n*Lc + l)*384 + i0 + kq];
        As[kq][aRow] = av.x; As[kq+1][aRow] = av.y; As[kq+2][aRow] = av.z; As[kq+3][aRow] = av.w;
        int bK = tid >> 4, nq = (tid & 15)*4;
        float4 bv = make_float4(0.f, 0.f, 0.f, 0.f);
        if (nq < 48) bv = *(const float4*)&Bw[(size_t)(kc + bK)*48 + nq];
        *(float4*)&Bs[bK][nq] = bv;
        __syncthreads();
        GEMM_INNER
        __syncthreads();
    }
    int g = phase*2 + s;
    #pragma unroll
    for (int r = 0; r < 4; ++r) {
        int row = row0 + ty4 + r;
        int n = row / Qlen, q = row - n*Qlen;
        #pragma unroll
        for (int j = 0; j < 4; ++j) {
            int c = tx4 + j;
            if (c < 48) {
                float v = acc[r][j] + Tb[g*48 + c];
                if (phase == 0) {
                    int b = n >> 9, tpos = n & 511;
                    size_t oi = ((size_t)(b*48 + c)*512 + tpos)*65 + q;
                    const float* res = s ? x1 : x0;
                    g_io[(size_t)s*TSZ + oi] = v + res[oi];
                } else {
                    int b = n / 65, f = n - b*65;
                    size_t oi = ((size_t)(b*48 + c)*512 + q)*65 + f;
                    g_eo[(size_t)s*TSZ + oi] = v + g_io[(size_t)s*TSZ + oi];
                }
            }
        }
    }
}

// ---------------- q/k/v head projections + leaky + LN ----------------
__global__ void __launch_bounds__(256) qkv_kernel(
    const float* __restrict__ AWqk, const float* __restrict__ Abqk, const float* __restrict__ Aaqk,
    const float* __restrict__ Agqk, const float* __restrict__ Abgqk,
    const float* __restrict__ AWv,  const float* __restrict__ Abv,  const float* __restrict__ Aav,
    const float* __restrict__ Agv,  const float* __restrict__ Abgv)
{
    int t = blockIdx.x, b = blockIdx.y, s = blockIdx.z, tid = threadIdx.x;
    __shared__ float zs[3120];
    __shared__ float buf[780];
    __shared__ float red[512];
    const float* z = g_eo + (size_t)s*TSZ;
    for (int i = tid; i < 3120; i += 256) {
        int c = i / 65, f = i - c*65;
        zs[i] = z[((size_t)(b*48 + c)*512 + t)*65 + f];
    }
    __syncthreads();
    for (int grp = 0; grp < 12; ++grp) {
        int tensor = grp >> 2, h = grp & 3;
        int nvals;
        const float *W, *bb, *gam, *bet;
        float alpha;
        float* outp;
        if (tensor < 2) {
            nvals = 520;
            int hh = (s*2 + tensor)*4 + h;
            W = AWqk + (size_t)hh*8*48; bb = Abqk + hh*8; alpha = Aaqk[hh];
            gam = Agqk + (size_t)hh*8*65; bet = Abgqk + (size_t)hh*8*65;
            outp = (tensor == 0 ? g_q : g_k) + ((size_t)((s*16 + b*4 + h)*512) + t)*520;
        } else {
            nvals = 780;
            int hh = s*4 + h;
            W = AWv + (size_t)hh*12*48; bb = Abv + hh*12; alpha = Aav[hh];
            gam = Agv + (size_t)hh*12*65; bet = Abgv + (size_t)hh*12*65;
            outp = g_v + ((size_t)((s*16 + b*4 + h)*512) + t)*780;
        }
        float ls = 0.f, lq = 0.f;
        for (int idx = tid; idx < nvals; idx += 256) {
            int e = idx / 65, f = idx - e*65;
            float a = bb[e];
            const float* wr = W + e*48;
            #pragma unroll
            for (int c = 0; c < 48; ++c) a += zs[c*65 + f]*wr[c];
            a = a >= 0.f ? a : alpha*a;
            buf[idx] = a; ls += a; lq += a*a;
        }
        red[tid] = ls; red[256 + tid] = lq;
        __syncthreads();
        for (int st = 128; st > 0; st >>= 1) {
            if (tid < st) { red[tid] += red[tid + st]; red[256 + tid] += red[256 + tid + st]; }
            __syncthreads();
        }
        float mu = red[0] / nvals;
        float inv = rsqrtf(red[256] / nvals - mu*mu + EPSLN);
        for (int idx = tid; idx < nvals; idx += 256)
            outp[idx] = (buf[idx] - mu)*inv*gam[idx] + bet[idx];
        __syncthreads();
    }
}

// ---------------- QK^T (scaled) ----------------
__global__ void __launch_bounds__(256) qk_gemm()
{
    __shared__ __align__(16) float As[16][68];
    __shared__ __align__(16) float Bs[16][68];
    int bz = blockIdx.z;
    const float* Q  = g_q + (size_t)bz*512*520;
    const float* Kf = g_k + (size_t)bz*512*520;
    float* Co = g_attn + (size_t)bz*512*512;
    int row0 = blockIdx.y*64, col0 = blockIdx.x*64;
    int tid = threadIdx.x, tx = tid & 15, ty = tid >> 4;
    int ty4 = ty*4, tx4 = tx*4;
    float acc[4][4] = {};
    for (int kc = 0; kc < 520; kc += 16) {
        int aRow = tid >> 2, kq = (tid & 3)*4;
        int gr = row0 + aRow;
        #pragma unroll
        for (int jj = 0; jj < 4; ++jj) {
            int kk = kc + kq + jj;
            As[kq + jj][aRow] = (kk < 520) ? Q[(size_t)gr*520 + kk] : 0.f;
        }
        int bCol = tid >> 2, kq2 = (tid & 3)*4;
        #pragma unroll
        for (int jj = 0; jj < 4; ++jj) {
            int kk = kc + kq2 + jj;
            Bs[kq2 + jj][bCol] = (kk < 520) ? Kf[(size_t)(col0 + bCol)*520 + kk] : 0.f;
        }
        __syncthreads();
        GEMM_INNER
        __syncthreads();
    }
    float rs = rsqrtf(520.f);
    #pragma unroll
    for (int r = 0; r < 4; ++r) {
        int row = row0 + ty4 + r;
        #pragma unroll
        for (int j = 0; j < 4; ++j)
            Co[(size_t)row*512 + col0 + tx4 + j] = acc[r][j]*rs;
    }
}

// ---------------- row softmax ----------------
__global__ void __launch_bounds__(256) softmax_rows()
{
    int row = blockIdx.x, bz = blockIdx.y, tid = threadIdx.x;
    float* p = g_attn + (size_t)bz*512*512 + (size_t)row*512;
    __shared__ float sm[512];
    __shared__ float red[256];
    sm[tid] = p[tid]; sm[tid + 256] = p[tid + 256];
    red[tid] = fmaxf(sm[tid], sm[tid + 256]);
    __syncthreads();
    for (int st = 128; st > 0; st >>= 1) {
        if (tid < st) red[tid] = fmaxf(red[tid], red[tid + st]);
        __syncthreads();
    }
    float mx = red[0];
    __syncthreads();
    float e0 = expf(sm[tid] - mx), e1 = expf(sm[tid + 256] - mx);
    red[tid] = e0 + e1;
    __syncthreads();
    for (int st = 128; st > 0; st >>= 1) {
        if (tid < st) red[tid] += red[tid + st];
        __syncthreads();
    }
    float invs = 1.f / red[0];
    p[tid] = e0*invs; p[tid + 256] = e1*invs;
}

// ---------------- P @ V ----------------
__global__ void __launch_bounds__(256) pv_gemm()
{
    __shared__ __align__(16) float As[16][68];
    __shared__ __align__(16) float Bs[16][68];
    int bz = blockIdx.z;
    const float* A  = g_attn + (size_t)bz*512*512;
    const float* Bv = g_v + (size_t)bz*512*780;
    float* Co = g_av + (size_t)bz*512*780;
    int row0 = blockIdx.y*64, col0 = blockIdx.x*64;
    int tid = threadIdx.x, tx = tid & 15, ty = tid >> 4;
    int ty4 = ty*4, tx4 = tx*4;
    float acc[4][4] = {};
    for (int kc = 0; kc < 512; kc += 16) {
        int aRow = tid >> 2, kq = (tid & 3)*4;
        int gr = row0 + aRow;
        float4 av = *(const float4*)&A[(size_t)gr*512 + kc + kq];
        As[kq][aRow] = av.x; As[kq+1][aRow] = av.y; As[kq+2][aRow] = av.z; As[kq+3][aRow] = av.w;
        int bK = tid >> 4, nq = (tid & 15)*4;
        int col = col0 + nq;
        float4 bv;
        if (col + 3 < 780) {
            bv = *(const float4*)&Bv[(size_t)(kc + bK)*780 + col];
        } else {
            bv.x = (col     < 780) ? Bv[(size_t)(kc + bK)*780 + col]     : 0.f;
            bv.y = (col + 1 < 780) ? Bv[(size_t)(kc + bK)*780 + col + 1] : 0.f;
            bv.z = (col + 2 < 780) ? Bv[(size_t)(kc + bK)*780 + col + 2] : 0.f;
            bv.w = (col + 3 < 780) ? Bv[(size_t)(kc + bK)*780 + col + 3] : 0.f;
        }
        *(float4*)&Bs[bK][nq] = bv;
        __syncthreads();
        GEMM_INNER
        __syncthreads();
    }
    #pragma unroll
    for (int r = 0; r < 4; ++r) {
        int row = row0 + ty4 + r;
        #pragma unroll
        for (int j = 0; j < 4; ++j) {
            int col = col0 + tx4 + j;
            if (col < 780) Co[(size_t)row*780 + col] = acc[r][j];
        }
    }
}

// ---------------- output projection + leaky + LN + residual ----------------
__global__ void __launch_bounds__(256) outproj_kernel(
    const float* __restrict__ AWp, const float* __restrict__ Abp, const float* __restrict__ Aap,
    const float* __restrict__ Agp, const float* __restrict__ Abgp, float* __restrict__ dout)
{
    int t = blockIdx.x, b = blockIdx.y, s = blockIdx.z, tid = threadIdx.x;
    __shared__ float os[3120];
    __shared__ float buf[3120];
    __shared__ float red[512];
    for (int i = tid; i < 3120; i += 256) {
        int c = i / 65, f = i - c*65;
        int h = c / 12, dv = c - h*12;
        os[i] = g_av[((size_t)((s*16 + b*4 + h)*512) + t)*780 + dv*65 + f];
    }
    __syncthreads();
    float alpha = Aap[s];
    float ls = 0.f, lq = 0.f;
    for (int idx = tid; idx < 3120; idx += 256) {
        int o = idx / 65, f = idx - o*65;
        float a = Abp[s*48 + o];
        const float* wr = AWp + (size_t)(s*48 + o)*48;
        #pragma unroll
        for (int c = 0; c < 48; ++c) a += os[c*65 + f]*wr[c];
        a = a >= 0.f ? a : alpha*a;
        buf[idx] = a; ls += a; lq += a*a;
    }
    red[tid] = ls; red[256 + tid] = lq;
    __syncthreads();
    for (int st = 128; st > 0; st >>= 1) {
        if (tid < st) { red[tid] += red[tid + st]; red[256 + tid] += red[256 + tid + st]; }
        __syncthreads();
    }
    float mu = red[0] / 3120.f;
    float inv = rsqrtf(red[256] / 3120.f - mu*mu + EPSLN);
    for (int idx = tid; idx < 3120; idx += 256) {
        int o = idx / 65, f = idx - o*65;
        float v = (buf[idx] - mu)*inv*Agp[(s*48 + o)*65 + f] + Abgp[(s*48 + o)*65 + f]
                + g_eo[(size_t)s*TSZ + ((size_t)(b*48 + o)*512 + t)*65 + f];
        dout[(((size_t)(s*4 + b)*48 + o)*512 + t)*65 + f] = v;
    }
}

// ---------------- host launch ----------------
extern "C" void kernel_launch(void* const* d_in, const int* in_sizes, int n_in,
                              void* d_out, int out_size)
{
    const float* x     = (const float*)d_in[0];
    const float* c2    = (const float*)d_in[1];
    const float* ng    = (const float*)d_in[2];
    const float* nb    = (const float*)d_in[3];
    const float* LWih  = (const float*)d_in[4];
    const float* LWhh  = (const float*)d_in[5];
    const float* Lb    = (const float*)d_in[6];
    const float* TW    = (const float*)d_in[7];
    const float* Tb    = (const float*)d_in[8];
    const float* AWqk  = (const float*)d_in[9];
    const float* Abqk  = (const float*)d_in[10];
    const float* Aaqk  = (const float*)d_in[11];
    const float* Agqk  = (const float*)d_in[12];
    const float* Abgqk = (const float*)d_in[13];
    const float* AWv   = (const float*)d_in[14];
    const float* Abv   = (const float*)d_in[15];
    const float* Aav   = (const float*)d_in[16];
    const float* Agv   = (const float*)d_in[17];
    const float* Abgv  = (const float*)d_in[18];
    const float* AWp   = (const float*)d_in[19];
    const float* Abp   = (const float*)d_in[20];
    const float* Aap   = (const float*)d_in[21];
    const float* Agp   = (const float*)d_in[22];
    const float* Abgp  = (const float*)d_in[23];
    float* out = (float*)d_out;

    pack_weights<<<512, 256>>>(LWih, LWhh, Lb, TW);

    // ---- phase 0: intra ----
    zero_state<<<512, 256>>>();
    ln_unfold_intra<<<dim3(512, 4, 2), 256>>>(x, c2, ng, nb);
    xw_gemm<<<dim3(12, (ROWS0 + 63)/64, 4), 256>>>(0, ROWS0);
    for (int t = 0; t < L0; ++t)
        lstm_step<<<dim3(12, 32, 4), 256>>>(t, 0, t & 1, N0, L0);
    convt_gemm<<<dim3(1, CONV_ROWS/64, 2), 256>>>(0, Tb, x, c2);

    // ---- phase 1: inter ----
    zero_state<<<512, 256>>>();
    ln_unfold_inter<<<dim3(512, 4, 2), 256>>>(ng, nb);
    xw_gemm<<<dim3(12, (ROWS1 + 63)/64, 4), 256>>>(1, ROWS1);
    for (int t = 0; t < L1; ++t)
        lstm_step<<<dim3(12, 5, 4), 256>>>(t, 1, t & 1, N1, L1);
    convt_gemm<<<dim3(1, CONV_ROWS/64, 2), 256>>>(1, Tb, x, c2);

    // ---- attention ----
    qkv_kernel<<<dim3(512, 4, 2), 256>>>(AWqk, Abqk, Aaqk, Agqk, Abgqk,
                                         AWv, Abv, Aav, Agv, Abgv);
    qk_gemm<<<dim3(8, 8, 32), 256>>>();
    softmax_rows<<<dim3(512, 32), 256>>>();
    pv_gemm<<<dim3(13, 8, 32), 256>>>();
    outproj_kernel<<<dim3(512, 4, 2), 256>>>(AWp, Abp, Aap, Agp, Abgp, out);
}

// round 8
// speedup vs baseline: 1.5273x; 1.5273x over previous
#include <cuda_runtime.h>
#include <cuda_bf16.h>
#include <math.h>
#include <stdint.h>

// ---------------- constants ----------------
#define Bb 4
#define Cc 48
#define Tt 512
#define Ff 65
#define L0 62
#define L1 509
#define N0 2048
#define N1 260
#define ROWS0 126976
#define ROWS1 132340
#define ROWSMAX 132340
#define CONV_ROWS 133120
#define XU_S  (ROWSMAX*192)
#define XW_S  ((size_t)ROWSMAX*768)
#define HS_S  ((size_t)ROWSMAX*384)
#define TSZ   (Bb*Cc*Tt*Ff)
#define EK    528            // padded E*F (520 -> 528)
#define EPSLN 1e-5f

// ---------------- device scratch ----------------
__device__ float g_xu[2*XU_S];
__device__ float g_xw[4*XW_S];
__device__ float g_hseq[2*HS_S];
__device__ float g_h[2*4*2048*192];
__device__ float g_c[4*2048*192];
__device__ float g_wihp[8*192*768];
__device__ float g_whhp[8*192*768];
__device__ float g_bp[8*768];
__device__ float g_twt[4*1536*48];
__device__ float g_io[2*TSZ];
__device__ float g_eo[2*TSZ];
__device__ float g_q[(size_t)2*16*512*EK];
__device__ float g_k[(size_t)2*16*512*EK];
__device__ float g_v[2*16*512*780];
__device__ float g_attn[(size_t)2*16*512*512];
__device__ float g_av[2*16*512*780];

__device__ __forceinline__ float sigf(float x){ return 1.f/(1.f+expf(-x)); }

__device__ __forceinline__ float tf32r(float x){
    uint32_t r; asm("cvt.rna.tf32.f32 %0, %1;" : "=r"(r) : "f"(x));
    return __uint_as_float(r);
}

__device__ __forceinline__ void mma_tf32(float* c, uint32_t a0, uint32_t a1,
                                         uint32_t a2, uint32_t a3,
                                         uint32_t b0, uint32_t b1){
    asm volatile("mma.sync.aligned.m16n8k8.row.col.f32.tf32.tf32.f32 "
        "{%0,%1,%2,%3}, {%4,%5,%6,%7}, {%8,%9}, {%0,%1,%2,%3};"
        : "+f"(c[0]), "+f"(c[1]), "+f"(c[2]), "+f"(c[3])
        : "r"(a0), "r"(a1), "r"(a2), "r"(a3), "r"(b0), "r"(b1));
}

// common per-thread mma ids (requires: int tid)
#define MMA_IDS \
    int lane = tid & 31, warp = tid >> 5; \
    int wm = warp >> 1, wn = warp & 1;    \
    int gp = lane >> 2, qn = lane & 3;    \
    int m0 = wm*16 + gp;                  \
    int nb0 = wn*32 + gp;

// one K=16 chunk of mma on As/Bs (uint32_t As[16][72], Bs[16][72]); acc[4][4]
#define MMA_CHUNK \
    _Pragma("unroll") \
    for (int h8 = 0; h8 < 2; ++h8) { \
        const int kb = h8*8 + qn; \
        uint32_t a0 = As[kb][m0], a1 = As[kb][m0+8]; \
        uint32_t a2 = As[kb+4][m0], a3 = As[kb+4][m0+8]; \
        mma_tf32(acc[0], a0,a1,a2,a3, Bs[kb][nb0],    Bs[kb+4][nb0]); \
        mma_tf32(acc[1], a0,a1,a2,a3, Bs[kb][nb0+8],  Bs[kb+4][nb0+8]); \
        mma_tf32(acc[2], a0,a1,a2,a3, Bs[kb][nb0+16], Bs[kb+4][nb0+16]); \
        mma_tf32(acc[3], a0,a1,a2,a3, Bs[kb][nb0+24], Bs[kb+4][nb0+24]); \
    }

// transposed A load: As[k][m] from row-major A (requires tid, row0, kc)
#define LOAD_A_TRANS(Aptr, lda, rowClamp) { \
    int aRow = tid >> 2, ak = (tid & 3)*4; \
    int gr = row0 + aRow; if (gr > (rowClamp)) gr = (rowClamp); \
    float4 v = *(const float4*)&(Aptr)[(size_t)gr*(lda) + kc + ak]; \
    As[ak  ][aRow] = __float_as_uint(v.x); As[ak+1][aRow] = __float_as_uint(v.y); \
    As[ak+2][aRow] = __float_as_uint(v.z); As[ak+3][aRow] = __float_as_uint(v.w); }

// direct B load: Bs[k][n] from k-major B (requires tid, col0, kc)
#define LOAD_B_DIRECT(Bptr, ldb) { \
    int bk = tid >> 4, bn4 = (tid & 15)*4; \
    float4 v = *(const float4*)&(Bptr)[(size_t)(kc + bk)*(ldb) + col0 + bn4]; \
    Bs[bk][bn4  ] = __float_as_uint(v.x); Bs[bk][bn4+1] = __float_as_uint(v.y); \
    Bs[bk][bn4+2] = __float_as_uint(v.z); Bs[bk][bn4+3] = __float_as_uint(v.w); }

// ---------------- weight packing (weights pre-rounded to tf32) ----------------
__global__ void pack_weights(const float* __restrict__ LWih, const float* __restrict__ LWhh,
                             const float* __restrict__ Lb,   const float* __restrict__ TW)
{
    int stride = gridDim.x * blockDim.x;
    int t0 = blockIdx.x * blockDim.x + threadIdx.x;
    for (int idx = t0; idx < 8*192*768; idx += stride) {
        int w = idx / (192*768);
        int r = idx - w*(192*768);
        int j = r / 768, col = r - j*768;
        int u = col >> 2, gt = col & 3;
        int g = (w>>2)*2 + ((w>>1)&1);
        int d = w & 1;
        size_t src = ((size_t)(g*2+d)*768 + gt*192 + u);
        g_wihp[idx] = tf32r(LWih[src*192 + j]);
        g_whhp[idx] = tf32r(LWhh[src*192 + j]);
    }
    for (int idx = t0; idx < 8*768; idx += stride) {
        int w = idx / 768, col = idx - w*768;
        int u = col >> 2, gt = col & 3;
        int g = (w>>2)*2 + ((w>>1)&1);
        int d = w & 1;
        g_bp[idx] = Lb[(g*2+d)*768 + gt*192 + u];
    }
    for (int idx = t0; idx < 4*1536*48; idx += stride) {
        int g = idx / (1536*48);
        int r = idx - g*(1536*48);
        int kk = r / 48, o = r - kk*48;
        int k = kk / 384, i = kk - k*384;
        g_twt[idx] = tf32r(TW[(((size_t)g*384 + i)*48 + o)*4 + k]);
    }
}

__global__ void zero_state()
{
    int stride = gridDim.x * blockDim.x;
    int t0 = blockIdx.x * blockDim.x + threadIdx.x;
    for (int i = t0; i < 2*4*2048*192; i += stride) g_h[i] = 0.f;
    for (int i = t0; i < 4*2048*192;   i += stride) g_c[i] = 0.f;
}

// ---------------- LN over C + unfold, intra ----------------
__global__ void ln_unfold_intra(const float* __restrict__ x0, const float* __restrict__ x1,
                                const float* __restrict__ ng, const float* __restrict__ nb)
{
    int t = blockIdx.x, b = blockIdx.y, s = blockIdx.z;
    const float* src = s ? x1 : x0;
    __shared__ float zs[48*65];
    __shared__ float mu[65], inv[65];
    int tid = threadIdx.x;
    for (int i = tid; i < 48*65; i += 256) {
        int c = i / 65, f = i - c*65;
        zs[i] = src[((size_t)(b*48 + c)*512 + t)*65 + f];
    }
    __syncthreads();
    if (tid < 65) {
        float s1 = 0.f, s2 = 0.f;
        #pragma unroll
        for (int c = 0; c < 48; ++c) { float v = zs[c*65 + tid]; s1 += v; s2 += v*v; }
        float m = s1 * (1.f/48.f);
        mu[tid] = m;
        inv[tid] = rsqrtf(s2*(1.f/48.f) - m*m + EPSLN);
    }
    __syncthreads();
    size_t n = (size_t)b*512 + t;
    float* outp = g_xu + (size_t)s*XU_S + n*(size_t)L0*192;
    for (int i = tid; i < 48*L0*4; i += 256) {
        int c = i / (L0*4);
        int r = i - c*(L0*4);
        int l = r >> 2, k = r & 3;
        int q = l + k;
        float v = (zs[c*65 + q] - mu[q]) * inv[q] * ng[s*48 + c] + nb[s*48 + c];
        outp[(size_t)l*192 + c*4 + k] = v;
    }
}

// ---------------- LN over C + unfold, inter ----------------
__global__ void ln_unfold_inter(const float* __restrict__ ng, const float* __restrict__ nb)
{
    int t = blockIdx.x, b = blockIdx.y, s = blockIdx.z;
    const float* src = g_io + (size_t)s*TSZ;
    __shared__ float zs[48*65];
    __shared__ float mu[65], inv[65];
    int tid = threadIdx.x;
    for (int i = tid; i < 48*65; i += 256) {
        int c = i / 65, f = i - c*65;
        zs[i] = src[((size_t)(b*48 + c)*512 + t)*65 + f];
    }
    __syncthreads();
    if (tid < 65) {
        float s1 = 0.f, s2 = 0.f;
        #pragma unroll
        for (int c = 0; c < 48; ++c) { float v = zs[c*65 + tid]; s1 += v; s2 += v*v; }
        float m = s1 * (1.f/48.f);
        mu[tid] = m;
        inv[tid] = rsqrtf(s2*(1.f/48.f) - m*m + EPSLN);
    }
    __syncthreads();
    int gi = 2 + s;
    for (int i = tid; i < 48*65; i += 256) {
        int c = i / 65, f = i - c*65;
        float v = (zs[i] - mu[f]) * inv[f] * ng[gi*48 + c] + nb[gi*48 + c];
        size_t n = (size_t)b*65 + f;
        float* outp = g_xu + (size_t)s*XU_S + n*(size_t)L1*192;
        #pragma unroll
        for (int k = 0; k < 4; ++k) {
            int l = t - k;
            if (l >= 0 && l < L1) outp[(size_t)l*192 + c*4 + k] = v;
        }
    }
}

// ---------------- xw = xu @ Wih^T + b  (tf32 mma) ----------------
__global__ void __launch_bounds__(256) xw_gemm(int phase, int M)
{
    __shared__ uint32_t As[16][72];
    __shared__ uint32_t Bs[16][72];
    int combo = blockIdx.z;
    int s = combo >> 1;
    const float* A    = g_xu + (size_t)s*XU_S;
    const float* Bw   = g_wihp + (size_t)(phase*4 + combo)*192*768;
    const float* bias = g_bp + (size_t)(phase*4 + combo)*768;
    float* Co = g_xw + (size_t)combo*XW_S;
    int row0 = blockIdx.y*64, col0 = blockIdx.x*64;
    int tid = threadIdx.x;
    MMA_IDS
    float acc[4][4] = {};
    for (int kc = 0; kc < 192; kc += 16) {
        LOAD_A_TRANS(A, 192, M-1)
        LOAD_B_DIRECT(Bw, 768)
        __syncthreads();
        MMA_CHUNK
        __syncthreads();
    }
    int rlo = row0 + wm*16 + gp;
    #pragma unroll
    for (int nn = 0; nn < 4; ++nn) {
        int cb = col0 + wn*32 + nn*8 + 2*qn;
        float b0v = bias[cb], b1v = bias[cb+1];
        if (rlo < M) {
            float2 v = make_float2(acc[nn][0] + b0v, acc[nn][1] + b1v);
            *(float2*)&Co[(size_t)rlo*768 + cb] = v;
        }
        if (rlo + 8 < M) {
            float2 v = make_float2(acc[nn][2] + b0v, acc[nn][3] + b1v);
            *(float2*)&Co[(size_t)(rlo+8)*768 + cb] = v;
        }
    }
}

// ---------------- fused LSTM step (tf32 mma recurrent GEMM) ----------------
__global__ void __launch_bounds__(256) lstm_step(int t, int phase, int parity, int Nseq, int Lc)
{
    __shared__ uint32_t As[16][72];
    __shared__ uint32_t Bs[16][72];
    __shared__ float Cs[64][68];
    int combo = blockIdx.z;
    int s = combo >> 1, d = combo & 1;
    int tt = d ? (Lc - 1 - t) : t;
    const float* Ah = g_h + ((size_t)parity*4 + combo)*2048*192;
    float* Ho       = g_h + ((size_t)(parity ^ 1)*4 + combo)*2048*192;
    float* Cst      = g_c + (size_t)combo*2048*192;
    const float* Bw = g_whhp + (size_t)(phase*4 + combo)*192*768;
    const float* XW = g_xw + (size_t)combo*XW_S;
    float* hs = g_hseq + (size_t)s*HS_S;
    int row0 = blockIdx.y*64, col0 = blockIdx.x*64;
    int tid = threadIdx.x;
    MMA_IDS
    float acc[4][4] = {};
    for (int kc = 0; kc < 192; kc += 16) {
        LOAD_A_TRANS(Ah, 192, Nseq-1)
        LOAD_B_DIRECT(Bw, 768)
        __syncthreads();
        MMA_CHUNK
        __syncthreads();
    }
    // stage gates to shared so each thread owns all 4 gates of one unit
    {
        int rlo = wm*16 + gp;
        #pragma unroll
        for (int nn = 0; nn < 4; ++nn) {
            int cb = wn*32 + nn*8 + 2*qn;
            Cs[rlo][cb] = acc[nn][0];   Cs[rlo][cb+1] = acc[nn][1];
            Cs[rlo+8][cb] = acc[nn][2]; Cs[rlo+8][cb+1] = acc[nn][3];
        }
    }
    __syncthreads();
    int tx = tid & 15, ty = tid >> 4;
    int u = (col0 >> 2) + tx;
    #pragma unroll
    for (int r = 0; r < 4; ++r) {
        int row = row0 + ty*4 + r;
        if (row < Nseq) {
            float4 gv = *(const float4*)&Cs[ty*4 + r][tx*4];
            float4 xv = *(const float4*)&XW[((size_t)row*Lc + tt)*768 + col0 + tx*4];
            float ig = gv.x + xv.x, fg = gv.y + xv.y, gg = gv.z + xv.z, og = gv.w + xv.w;
            float cprev = Cst[(size_t)row*192 + u];
            float cn = sigf(fg)*cprev + sigf(ig)*tanhf(gg);
            float hn = sigf(og)*tanhf(cn);
            Cst[(size_t)row*192 + u] = cn;
            Ho[(size_t)row*192 + u] = hn;
            hs[((size_t)row*Lc + tt)*384 + d*192 + u] = hn;
        }
    }
}

// ---------------- convT1d gather-GEMM + bias + residual (tf32 mma) ----------------
__global__ void __launch_bounds__(256) convt_gemm(int phase, const float* __restrict__ Tb,
                                                  const float* __restrict__ x0, const float* __restrict__ x1)
{
    __shared__ uint32_t As[16][72];
    __shared__ uint32_t Bs[16][72];
    int s = blockIdx.z;
    int Lc   = phase ? L1 : L0;
    int Qlen = phase ? 512 : 65;
    const float* hs = g_hseq + (size_t)s*HS_S;
    const float* Bw = g_twt + (size_t)(phase*2 + s)*1536*48;
    int row0 = blockIdx.y*64;
    int tid = threadIdx.x;
    MMA_IDS
    float acc[4][4] = {};
    for (int kc = 0; kc < 1536; kc += 16) {
        int ktap = kc / 384;
        int i0 = kc - ktap*384;
        {   // gathered A rows (transposed store, zero fill)
            int aRow = tid >> 2, ak = (tid & 3)*4;
            int gr = row0 + aRow;
            int n = gr / Qlen, q = gr - n*Qlen;
            int l = q - ktap;
            float4 v = make_float4(0.f, 0.f, 0.f, 0.f);
            if (l >= 0 && l < Lc)
                v = *(const float4*)&hs[((size_t)n*Lc + l)*384 + i0 + ak];
            As[ak  ][aRow] = __float_as_uint(v.x); As[ak+1][aRow] = __float_as_uint(v.y);
            As[ak+2][aRow] = __float_as_uint(v.z); As[ak+3][aRow] = __float_as_uint(v.w);
        }
        {   // B tile (N=48 < 64, zero pad)
            int bk = tid >> 4, bn4 = (tid & 15)*4;
            float4 v = make_float4(0.f, 0.f, 0.f, 0.f);
            if (bn4 < 48) v = *(const float4*)&Bw[(size_t)(kc + bk)*48 + bn4];
            Bs[bk][bn4  ] = __float_as_uint(v.x); Bs[bk][bn4+1] = __float_as_uint(v.y);
            Bs[bk][bn4+2] = __float_as_uint(v.z); Bs[bk][bn4+3] = __float_as_uint(v.w);
        }
        __syncthreads();
        MMA_CHUNK
        __syncthreads();
    }
    int g = phase*2 + s;
    int rlo = row0 + wm*16 + gp;
    #pragma unroll
    for (int nn = 0; nn < 4; ++nn) {
        int cb = wn*32 + nn*8 + 2*qn;
        #pragma unroll
        for (int half = 0; half < 2; ++half) {
            int row = rlo + half*8;
            int n = row / Qlen, q = row - n*Qlen;
            #pragma unroll
            for (int j = 0; j < 2; ++j) {
                int c = cb + j;
                if (c < 48) {
                    float v = acc[nn][half*2 + j] + Tb[g*48 + c];
                    if (phase == 0) {
                        int b = n >> 9, tpos = n & 511;
                        size_t oi = ((size_t)(b*48 + c)*512 + tpos)*65 + q;
                        const float* res = s ? x1 : x0;
                        g_io[(size_t)s*TSZ + oi] = v + res[oi];
                    } else {
                        int b = n / 65, f = n - b*65;
                        size_t oi = ((size_t)(b*48 + c)*512 + q)*65 + f;
                        g_eo[(size_t)s*TSZ + oi] = v + g_io[(size_t)s*TSZ + oi];
                    }
                }
            }
        }
    }
}

// ---------------- q/k/v head projections + leaky + LN ----------------
__global__ void __launch_bounds__(256) qkv_kernel(
    const float* __restrict__ AWqk, const float* __restrict__ Abqk, const float* __restrict__ Aaqk,
    const float* __restrict__ Agqk, const float* __restrict__ Abgqk,
    const float* __restrict__ AWv,  const float* __restrict__ Abv,  const float* __restrict__ Aav,
    const float* __restrict__ Agv,  const float* __restrict__ Abgv)
{
    int t = blockIdx.x, b = blockIdx.y, s = blockIdx.z, tid = threadIdx.x;
    __shared__ float zs[3120];
    __shared__ float buf[780];
    __shared__ float red[512];
    const float* z = g_eo + (size_t)s*TSZ;
    for (int i = tid; i < 3120; i += 256) {
        int c = i / 65, f = i - c*65;
        zs[i] = z[((size_t)(b*48 + c)*512 + t)*65 + f];
    }
    __syncthreads();
    for (int grp = 0; grp < 12; ++grp) {
        int tensor = grp >> 2, h = grp & 3;
        int nvals;
        const float *W, *bb, *gam, *bet;
        float alpha;
        float* outp;
        bool pad = false;
        if (tensor < 2) {
            nvals = 520;
            int hh = (s*2 + tensor)*4 + h;
            W = AWqk + (size_t)hh*8*48; bb = Abqk + hh*8; alpha = Aaqk[hh];
            gam = Agqk + (size_t)hh*8*65; bet = Abgqk + (size_t)hh*8*65;
            outp = (tensor == 0 ? g_q : g_k) + ((size_t)((s*16 + b*4 + h)*512) + t)*EK;
            pad = true;
        } else {
            nvals = 780;
            int hh = s*4 + h;
            W = AWv + (size_t)hh*12*48; bb = Abv + hh*12; alpha = Aav[hh];
            gam = Agv + (size_t)hh*12*65; bet = Abgv + (size_t)hh*12*65;
            outp = g_v + ((size_t)((s*16 + b*4 + h)*512) + t)*780;
        }
        float ls = 0.f, lq = 0.f;
        for (int idx = tid; idx < nvals; idx += 256) {
            int e = idx / 65, f = idx - e*65;
            float a = bb[e];
            const float* wr = W + e*48;
            #pragma unroll
            for (int c = 0; c < 48; ++c) a += zs[c*65 + f]*wr[c];
            a = a >= 0.f ? a : alpha*a;
            buf[idx] = a; ls += a; lq += a*a;
        }
        red[tid] = ls; red[256 + tid] = lq;
        __syncthreads();
        for (int st = 128; st > 0; st >>= 1) {
            if (tid < st) { red[tid] += red[tid + st]; red[256 + tid] += red[256 + tid + st]; }
            __syncthreads();
        }
        float mu = red[0] / nvals;
        float inv = rsqrtf(red[256] / nvals - mu*mu + EPSLN);
        for (int idx = tid; idx < nvals; idx += 256)
            outp[idx] = (buf[idx] - mu)*inv*gam[idx] + bet[idx];
        if (pad && tid < EK - 520) outp[520 + tid] = 0.f;
        __syncthreads();
    }
}

// ---------------- QK^T (scaled, tf32 mma) ----------------
__global__ void __launch_bounds__(256) qk_gemm()
{
    __shared__ uint32_t As[16][72];
    __shared__ uint32_t Bs[16][72];
    int bz = blockIdx.z;
    const float* Q  = g_q + (size_t)bz*512*EK;
    const float* Kf = g_k + (size_t)bz*512*EK;
    float* Co = g_attn + (size_t)bz*512*512;
    int row0 = blockIdx.y*64, col0 = blockIdx.x*64;
    int tid = threadIdx.x;
    MMA_IDS
    float acc[4][4] = {};
    for (int kc = 0; kc < EK; kc += 16) {
        LOAD_A_TRANS(Q, EK, 511)
        {   // B^T: Bs[k][n] = K[n][k]  (transposed store)
            int bRow = tid >> 2, bk = (tid & 3)*4;
            float4 v = *(const float4*)&Kf[(size_t)(col0 + bRow)*EK + kc + bk];
            Bs[bk  ][bRow] = __float_as_uint(v.x); Bs[bk+1][bRow] = __float_as_uint(v.y);
            Bs[bk+2][bRow] = __float_as_uint(v.z); Bs[bk+3][bRow] = __float_as_uint(v.w);
        }
        __syncthreads();
        MMA_CHUNK
        __syncthreads();
    }
    float rs = rsqrtf(520.f);
    int rlo = row0 + wm*16 + gp;
    #pragma unroll
    for (int nn = 0; nn < 4; ++nn) {
        int cb = col0 + wn*32 + nn*8 + 2*qn;
        *(float2*)&Co[(size_t)rlo*512 + cb]     = make_float2(acc[nn][0]*rs, acc[nn][1]*rs);
        *(float2*)&Co[(size_t)(rlo+8)*512 + cb] = make_float2(acc[nn][2]*rs, acc[nn][3]*rs);
    }
}

// ---------------- row softmax ----------------
__global__ void __launch_bounds__(256) softmax_rows()
{
    int row = blockIdx.x, bz = blockIdx.y, tid = threadIdx.x;
    float* p = g_attn + (size_t)bz*512*512 + (size_t)row*512;
    __shared__ float sm[512];
    __shared__ float red[256];
    sm[tid] = p[tid]; sm[tid + 256] = p[tid + 256];
    red[tid] = fmaxf(sm[tid], sm[tid + 256]);
    __syncthreads();
    for (int st = 128; st > 0; st >>= 1) {
        if (tid < st) red[tid] = fmaxf(red[tid], red[tid + st]);
        __syncthreads();
    }
    float mx = red[0];
    __syncthreads();
    float e0 = expf(sm[tid] - mx), e1 = expf(sm[tid + 256] - mx);
    red[tid] = e0 + e1;
    __syncthreads();
    for (int st = 128; st > 0; st >>= 1) {
        if (tid < st) red[tid] += red[tid + st];
        __syncthreads();
    }
    float invs = 1.f / red[0];
    p[tid] = e0*invs; p[tid + 256] = e1*invs;
}

// ---------------- P @ V (tf32 mma) ----------------
__global__ void __launch_bounds__(256) pv_gemm()
{
    __shared__ uint32_t As[16][72];
    __shared__ uint32_t Bs[16][72];
    int bz = blockIdx.z;
    const float* A  = g_attn + (size_t)bz*512*512;
    const float* Bv = g_v + (size_t)bz*512*780;
    float* Co = g_av + (size_t)bz*512*780;
    int row0 = blockIdx.y*64, col0 = blockIdx.x*64;
    int tid = threadIdx.x;
    MMA_IDS
    float acc[4][4] = {};
    for (int kc = 0; kc < 512; kc += 16) {
        LOAD_A_TRANS(A, 512, 511)
        {   // B direct with col guard (N=780)
            int bk = tid >> 4, bn4 = (tid & 15)*4;
            int col = col0 + bn4;
            float4 v;
            if (col + 3 < 780) {
                v = *(const float4*)&Bv[(size_t)(kc + bk)*780 + col];
            } else {
                v.x = (col     < 780) ? Bv[(size_t)(kc + bk)*780 + col]     : 0.f;
                v.y = (col + 1 < 780) ? Bv[(size_t)(kc + bk)*780 + col + 1] : 0.f;
                v.z = (col + 2 < 780) ? Bv[(size_t)(kc + bk)*780 + col + 2] : 0.f;
                v.w = (col + 3 < 780) ? Bv[(size_t)(kc + bk)*780 + col + 3] : 0.f;
            }
            Bs[bk][bn4  ] = __float_as_uint(v.x); Bs[bk][bn4+1] = __float_as_uint(v.y);
            Bs[bk][bn4+2] = __float_as_uint(v.z); Bs[bk][bn4+3] = __float_as_uint(v.w);
        }
        __syncthreads();
        MMA_CHUNK
        __syncthreads();
    }
    int rlo = row0 + wm*16 + gp;
    #pragma unroll
    for (int nn = 0; nn < 4; ++nn) {
        int cb = col0 + wn*32 + nn*8 + 2*qn;
        #pragma unroll
        for (int j = 0; j < 2; ++j) {
            int col = cb + j;
            if (col < 780) {
                Co[(size_t)rlo*780 + col]     = acc[nn][j];
                Co[(size_t)(rlo+8)*780 + col] = acc[nn][2 + j];
            }
        }
    }
}

// ---------------- output projection + leaky + LN + residual ----------------
__global__ void __launch_bounds__(256) outproj_kernel(
    const float* __restrict__ AWp, const float* __restrict__ Abp, const float* __restrict__ Aap,
    const float* __restrict__ Agp, const float* __restrict__ Abgp, float* __restrict__ dout)
{
    int t = blockIdx.x, b = blockIdx.y, s = blockIdx.z, tid = threadIdx.x;
    __shared__ float os[3120];
    __shared__ float buf[3120];
    __shared__ float red[512];
    for (int i = tid; i < 3120; i += 256) {
        int c = i / 65, f = i - c*65;
        int h = c / 12, dv = c - h*12;
        os[i] = g_av[((size_t)((s*16 + b*4 + h)*512) + t)*780 + dv*65 + f];
    }
    __syncthreads();
    float alpha = Aap[s];
    float ls = 0.f, lq = 0.f;
    for (int idx = tid; idx < 3120; idx += 256) {
        int o = idx / 65, f = idx - o*65;
        float a = Abp[s*48 + o];
        const float* wr = AWp + (size_t)(s*48 + o)*48;
        #pragma unroll
        for (int c = 0; c < 48; ++c) a += os[c*65 + f]*wr[c];
        a = a >= 0.f ? a : alpha*a;
        buf[idx] = a; ls += a; lq += a*a;
    }
    red[tid] = ls; red[256 + tid] = lq;
    __syncthreads();
    for (int st = 128; st > 0; st >>= 1) {
        if (tid < st) { red[tid] += red[tid + st]; red[256 + tid] += red[256 + tid + st]; }
        __syncthreads();
    }
    float mu = red[0] / 3120.f;
    float inv = rsqrtf(red[256] / 3120.f - mu*mu + EPSLN);
    for (int idx = tid; idx < 3120; idx += 256) {
        int o = idx / 65, f = idx - o*65;
        float v = (buf[idx] - mu)*inv*Agp[(s*48 + o)*65 + f] + Abgp[(s*48 + o)*65 + f]
                + g_eo[(size_t)s*TSZ + ((size_t)(b*48 + o)*512 + t)*65 + f];
        dout[(((size_t)(s*4 + b)*48 + o)*512 + t)*65 + f] = v;
    }
}

// ---------------- host launch ----------------
extern "C" void kernel_launch(void* const* d_in, const int* in_sizes, int n_in,
                              void* d_out, int out_size)
{
    const float* x     = (const float*)d_in[0];
    const float* c2    = (const float*)d_in[1];
    const float* ng    = (const float*)d_in[2];
    const float* nb    = (const float*)d_in[3];
    const float* LWih  = (const float*)d_in[4];
    const float* LWhh  = (const float*)d_in[5];
    const float* Lb    = (const float*)d_in[6];
    const float* TW    = (const float*)d_in[7];
    const float* Tb    = (const float*)d_in[8];
    const float* AWqk  = (const float*)d_in[9];
    const float* Abqk  = (const float*)d_in[10];
    const float* Aaqk  = (const float*)d_in[11];
    const float* Agqk  = (const float*)d_in[12];
    const float* Abgqk = (const float*)d_in[13];
    const float* AWv   = (const float*)d_in[14];
    const float* Abv   = (const float*)d_in[15];
    const float* Aav   = (const float*)d_in[16];
    const float* Agv   = (const float*)d_in[17];
    const float* Abgv  = (const float*)d_in[18];
    const float* AWp   = (const float*)d_in[19];
    const float* Abp   = (const float*)d_in[20];
    const float* Aap   = (const float*)d_in[21];
    const float* Agp   = (const float*)d_in[22];
    const float* Abgp  = (const float*)d_in[23];
    float* out = (float*)d_out;

    pack_weights<<<512, 256>>>(LWih, LWhh, Lb, TW);

    // ---- phase 0: intra ----
    zero_state<<<512, 256>>>();
    ln_unfold_intra<<<dim3(512, 4, 2), 256>>>(x, c2, ng, nb);
    xw_gemm<<<dim3(12, (ROWS0 + 63)/64, 4), 256>>>(0, ROWS0);
    for (int t = 0; t < L0; ++t)
        lstm_step<<<dim3(12, 32, 4), 256>>>(t, 0, t & 1, N0, L0);
    convt_gemm<<<dim3(1, CONV_ROWS/64, 2), 256>>>(0, Tb, x, c2);

    // ---- phase 1: inter ----
    zero_state<<<512, 256>>>();
    ln_unfold_inter<<<dim3(512, 4, 2), 256>>>(ng, nb);
    xw_gemm<<<dim3(12, (ROWS1 + 63)/64, 4), 256>>>(1, ROWS1);
    for (int t = 0; t < L1; ++t)
        lstm_step<<<dim3(12, 5, 4), 256>>>(t, 1, t & 1, N1, L1);
    convt_gemm<<<dim3(1, CONV_ROWS/64, 2), 256>>>(1, Tb, x, c2);

    // ---- attention ----
    qkv_kernel<<<dim3(512, 4, 2), 256>>>(AWqk, Abqk, Aaqk, Agqk, Abgqk,
                                         AWv, Abv, Aav, Agv, Abgv);
    qk_gemm<<<dim3(8, 8, 32), 256>>>();
    softmax_rows<<<dim3(512, 32), 256>>>();
    pv_gemm<<<dim3(13, 8, 32), 256>>>();
    outproj_kernel<<<dim3(512, 4, 2), 256>>>(AWp, Abp, Aap, Agp, Abgp, out);
}